// round 8
// baseline (speedup 1.0000x reference)
#include <cuda_runtime.h>
#include <cuda_bf16.h>
#include <cstdint>
#include <cstddef>

// ---------------------------------------------------------------------------
// MHA: B=2, S=2048, E=1024, H=16, D=64, fp32, causal. mma.sync bf16 split-hi/lo.
//  split3(x)->A', split3(wqkv)->B'
//  gemm1 (fused epi): Q'/K'/V' compact [hi(64)|lo(64)] bf16, per (b,h)
//  attn (BR=128, double-buffered K/V, 3-term chunk-paired QK) -> E' [hi|lo|hi]
//  split3(w0)->B' ; gemm2 -> fp32 out
// ---------------------------------------------------------------------------

#define S_LEN   2048
#define E_DIM   1024
#define K3      3072

__device__ __nv_bfloat16 g_a2[4096 * K3];            // X' then E'
__device__ __nv_bfloat16 g_w2[3072 * K3];            // Wqkv' then W0'
__device__ __nv_bfloat16 g_q [32 * 2048 * 128];      // Q' [hi|lo]
__device__ __nv_bfloat16 g_k [32 * 2048 * 128];      // K' [hi|lo]
__device__ __nv_bfloat16 g_v [32 * 2048 * 128];      // V' [hi|lo]

// ---------------------------------------------------------------------------
__device__ __forceinline__ uint32_t smem_u32(const void* p) {
    uint32_t a;
    asm("{ .reg .u64 t; cvta.to.shared.u64 t, %1; cvt.u32.u64 %0, t; }"
        : "=r"(a) : "l"(p));
    return a;
}
__device__ __forceinline__ uint32_t pk(__nv_bfloat16 a, __nv_bfloat16 b) {
    __nv_bfloat162 t = __halves2bfloat162(a, b);
    return *reinterpret_cast<uint32_t*>(&t);
}
__device__ __forceinline__ uint32_t pkf(float a, float b) {
    return pk(__float2bfloat16(a), __float2bfloat16(b));
}
__device__ __forceinline__ void ldsm4(uint32_t r[4], uint32_t addr) {
    asm volatile("ldmatrix.sync.aligned.m8n8.x4.shared.b16 {%0,%1,%2,%3}, [%4];"
                 : "=r"(r[0]), "=r"(r[1]), "=r"(r[2]), "=r"(r[3]) : "r"(addr));
}
__device__ __forceinline__ void ldsm4t(uint32_t r[4], uint32_t addr) {
    asm volatile("ldmatrix.sync.aligned.m8n8.x4.trans.shared.b16 {%0,%1,%2,%3}, [%4];"
                 : "=r"(r[0]), "=r"(r[1]), "=r"(r[2]), "=r"(r[3]) : "r"(addr));
}
__device__ __forceinline__ void mma16816(float c[4], const uint32_t a[4],
                                         uint32_t b0, uint32_t b1) {
    asm volatile("mma.sync.aligned.m16n8k16.row.col.f32.bf16.bf16.f32 "
                 "{%0,%1,%2,%3}, {%4,%5,%6,%7}, {%8,%9}, {%0,%1,%2,%3};"
                 : "+f"(c[0]), "+f"(c[1]), "+f"(c[2]), "+f"(c[3])
                 : "r"(a[0]), "r"(a[1]), "r"(a[2]), "r"(a[3]), "r"(b0), "r"(b1));
}
__device__ __forceinline__ void cpa16(uint32_t dst, const void* src) {
    asm volatile("cp.async.cg.shared.global [%0], [%1], 16;" :: "r"(dst), "l"(src));
}

// ---------------------------------------------------------------------------
// split3: fp32 [rows,K] -> bf16 [rows,3K]. loblk 1: [hi|lo|hi]; 2: [hi|hi|lo]
// ---------------------------------------------------------------------------
__global__ void split3_kernel(const float* __restrict__ src,
                              __nv_bfloat16* __restrict__ dst,
                              int rows, int K, int loblk) {
    int t = blockIdx.x * blockDim.x + threadIdx.x;
    int per4 = K >> 2;
    if (t >= rows * per4) return;
    int r = t / per4, c4 = (t - r * per4) * 4;
    float4 v = ((const float4*)src)[t];

    __nv_bfloat16 h0 = __float2bfloat16(v.x), h1 = __float2bfloat16(v.y);
    __nv_bfloat16 h2 = __float2bfloat16(v.z), h3 = __float2bfloat16(v.w);
    uint2 hp = make_uint2(pk(h0, h1), pk(h2, h3));
    uint2 lp = make_uint2(pkf(v.x - __bfloat162float(h0), v.y - __bfloat162float(h1)),
                          pkf(v.z - __bfloat162float(h2), v.w - __bfloat162float(h3)));

    __nv_bfloat16* d0 = dst + (size_t)r * (3 * K) + c4;
    *(uint2*)(d0)         = hp;
    *(uint2*)(d0 + K)     = (loblk == 1) ? lp : hp;
    *(uint2*)(d0 + 2 * K) = (loblk == 1) ? hp : lp;
}

// ---------------------------------------------------------------------------
// GEMM: C = A[M,K] @ B[N,K]^T. 128x128 tile, BK=64, 3-stage cp.async, 1 sync.
// mode 0: fp32 C.  mode 1: fused QKV split epilogue -> Qd/Kd/Vd [hi|lo].
// ---------------------------------------------------------------------------
#define BM 128
#define BN 128
#define BK 64
#define KSTRB 144                       // bytes per smem row (72 bf16, odd 16B)
#define STG_BYTES ((BM + BN) * KSTRB)   // 36864
#define GEMM_SMEM (3 * STG_BYTES)       // 110592

extern __shared__ char sh_raw[];

__global__ __launch_bounds__(256, 2)
void gemm_mma(const __nv_bfloat16* __restrict__ A,
              const __nv_bfloat16* __restrict__ B,
              float* __restrict__ C, int M, int N, int K, int mode,
              __nv_bfloat16* __restrict__ Qd,
              __nv_bfloat16* __restrict__ Kd,
              __nv_bfloat16* __restrict__ Vd) {
    const uint32_t sb = smem_u32(sh_raw);
    const int tid = threadIdx.x, wid = tid >> 5, lane = tid & 31;
    const int bm = blockIdx.y * BM, bn = blockIdx.x * BN;
    const int wm = (wid >> 2) * 64, wn = (wid & 3) * 32;
    const int g = lane >> 2, tg = lane & 3;
    const int lrow = lane & 15, lcol = (lane >> 4) * 8;

    auto load_stage = [&](int s, int kk) {
        uint32_t abase = sb + (uint32_t)s * STG_BYTES;
        uint32_t bbase = abase + BM * KSTRB;
#pragma unroll
        for (int i = 0; i < 8; ++i) {
            int c = tid + i * 256;
            if (c < 1024) {
                int row = c >> 3, k16 = c & 7;
                cpa16(abase + row * KSTRB + k16 * 16,
                      A + (size_t)(bm + row) * K + kk + k16 * 8);
            } else {
                int row = (c - 1024) >> 3, k16 = c & 7;
                cpa16(bbase + row * KSTRB + k16 * 16,
                      B + (size_t)(bn + row) * K + kk + k16 * 8);
            }
        }
        asm volatile("cp.async.commit_group;" ::: "memory");
    };

    float acc[4][4][4];
#pragma unroll
    for (int i = 0; i < 4; ++i)
#pragma unroll
        for (int j = 0; j < 4; ++j)
#pragma unroll
            for (int e = 0; e < 4; ++e) acc[i][j][e] = 0.0f;

    const int NC = K / BK;   // 48
    load_stage(0, 0);
    load_stage(1, BK);

    int st = 0;
    for (int c = 0; c < NC; ++c) {
        if (c + 1 < NC) asm volatile("cp.async.wait_group 1;" ::: "memory");
        else            asm volatile("cp.async.wait_group 0;" ::: "memory");
        __syncthreads();
        if (c + 2 < NC) {
            int ns = st + 2; if (ns >= 3) ns -= 3;
            load_stage(ns, (c + 2) * BK);
        }

        uint32_t abase = sb + (uint32_t)st * STG_BYTES;
        uint32_t bbase = abase + BM * KSTRB;
#pragma unroll
        for (int ks = 0; ks < 4; ++ks) {
            uint32_t a[4][4];
#pragma unroll
            for (int mt = 0; mt < 4; ++mt)
                ldsm4(a[mt], abase + (wm + mt * 16 + lrow) * KSTRB + (ks * 16 + lcol) * 2);
            uint32_t bf[4][2];
#pragma unroll
            for (int nb = 0; nb < 2; ++nb) {
                uint32_t r[4];
                ldsm4(r, bbase + (wn + nb * 16 + lrow) * KSTRB + (ks * 16 + lcol) * 2);
                bf[nb * 2][0] = r[0];     bf[nb * 2][1] = r[2];
                bf[nb * 2 + 1][0] = r[1]; bf[nb * 2 + 1][1] = r[3];
            }
#pragma unroll
            for (int mt = 0; mt < 4; ++mt)
#pragma unroll
                for (int nt = 0; nt < 4; ++nt)
                    mma16816(acc[mt][nt], a[mt], bf[nt][0], bf[nt][1]);
        }
        ++st; if (st >= 3) st = 0;
    }

    if (mode == 0) {
#pragma unroll
        for (int mt = 0; mt < 4; ++mt) {
            int r0 = bm + wm + mt * 16 + g;
#pragma unroll
            for (int nt = 0; nt < 4; ++nt) {
                int col = bn + wn + nt * 8 + tg * 2;
                *(float2*)(C + (size_t)r0 * N + col) =
                    make_float2(acc[mt][nt][0], acc[mt][nt][1]);
                *(float2*)(C + (size_t)(r0 + 8) * N + col) =
                    make_float2(acc[mt][nt][2], acc[mt][nt][3]);
            }
        }
    } else {
        // fused QKV split epilogue: [hi(64)|lo(64)] rows of 128 per (b,h)
#pragma unroll
        for (int nt = 0; nt < 4; ++nt) {
            int cbase = bn + wn + nt * 8 + tg * 2;
            int plane = cbase >> 10, rem = cbase & 1023;
            int h = rem >> 6, d = rem & 63;
            __nv_bfloat16* basep = (plane == 0) ? Qd : (plane == 1) ? Kd : Vd;
#pragma unroll
            for (int mt = 0; mt < 4; ++mt) {
#pragma unroll
                for (int rr = 0; rr < 2; ++rr) {
                    int row = bm + wm + mt * 16 + g + rr * 8;
                    int b = row >> 11, s = row & 2047;
                    float v0 = acc[mt][nt][rr * 2], v1 = acc[mt][nt][rr * 2 + 1];
                    __nv_bfloat16 h0 = __float2bfloat16(v0), h1 = __float2bfloat16(v1);
                    uint32_t hi = pk(h0, h1);
                    uint32_t lo = pkf(v0 - __bfloat162float(h0), v1 - __bfloat162float(h1));
                    __nv_bfloat16* p = basep +
                        ((size_t)(b * 16 + h) * 2048 + s) * 128 + d;
                    *(uint32_t*)(p)      = hi;
                    *(uint32_t*)(p + 64) = lo;
                }
            }
        }
    }
}

// ---------------------------------------------------------------------------
// Flash attention v3c: BR=128, BC=64, 256 threads, causal, double-buffered K/V.
// Q/K/V compact [hi|lo] (128 cols); FIXED loads (16 chunks per 128-col row).
// Writes E' split [hi|lo|hi] to g_a2.
// ---------------------------------------------------------------------------
#define STR 136   // smem stride (elements), odd multiple of 8
#define Q_EL  (128 * STR)
#define KV_EL (64 * STR)
#define ATT_SMEM ((Q_EL + 4 * KV_EL) * 2)   // 104448 B

__global__ __launch_bounds__(256, 2)
void attn_mma3(const __nv_bfloat16* __restrict__ Qg,
               const __nv_bfloat16* __restrict__ Kg,
               const __nv_bfloat16* __restrict__ Vg,
               __nv_bfloat16* __restrict__ Eo) {
    const uint32_t sbQ = smem_u32(sh_raw);

    const int tid = threadIdx.x, wid = tid >> 5, lane = tid & 31;
    const int qi = (gridDim.x - 1) - blockIdx.x;     // big tiles first
    const int q0 = qi * 128;
    const int h = blockIdx.y, b = blockIdx.z;
    const size_t bh = (size_t)(b * 16 + h);
    const int g = lane >> 2, tg = lane & 3;
    const int lrow = lane & 15, lcol = (lane >> 4) * 8;

    auto load_kv = [&](int buf, int k0) {
        uint32_t kb = sbQ + (Q_EL + buf * 2 * KV_EL) * 2;
        uint32_t vb = kb + KV_EL * 2;
        const __nv_bfloat16* kg = Kg + (bh * 2048 + k0) * 128;
        const __nv_bfloat16* vg = Vg + (bh * 2048 + k0) * 128;
#pragma unroll
        for (int i = 0; i < 4; ++i) {
            int c = tid + i * 256;           // 1024 chunks: 64 rows x 16
            int row = c >> 4, cg = c & 15;
            cpa16(kb + (row * STR + cg * 8) * 2, kg + row * 128 + cg * 8);
            cpa16(vb + (row * STR + cg * 8) * 2, vg + row * 128 + cg * 8);
        }
        asm volatile("cp.async.commit_group;" ::: "memory");
    };

    // prologue: Q tile (128 x 128 -> 2048 chunks) + first K/V tile
    {
        const __nv_bfloat16* qg = Qg + (bh * 2048 + q0) * 128;
#pragma unroll
        for (int i = 0; i < 8; ++i) {
            int c = tid + i * 256;           // 2048 chunks: 128 rows x 16
            int row = c >> 4, cg = c & 15;
            cpa16(sbQ + (row * STR + cg * 8) * 2, qg + row * 128 + cg * 8);
        }
        asm volatile("cp.async.commit_group;" ::: "memory");
    }
    load_kv(0, 0);

    float m0 = -1e30f, m1 = -1e30f, l0 = 0.0f, l1 = 0.0f;
    float o[8][4];
#pragma unroll
    for (int i = 0; i < 8; ++i)
#pragma unroll
        for (int j = 0; j < 4; ++j) o[i][j] = 0.0f;

    const int ntiles = 2 * qi + 2;
    const int rowg0 = q0 + wid * 16 + g, rowg1 = rowg0 + 8;

    for (int t = 0; t < ntiles; ++t) {
        const int k0 = t * 64;
        asm volatile("cp.async.wait_group 0;" ::: "memory");
        __syncthreads();   // tile t data visible; all warps done with buf (t+1)&1
        if (t + 1 < ntiles) load_kv((t + 1) & 1, (t + 1) * 64);

        const uint32_t kbase = sbQ + (Q_EL + (t & 1) * 2 * KV_EL) * 2;
        const uint32_t vbase = kbase + KV_EL * 2;

        // ---- S = 3-term QK^T: (qhi,khi), (qlo,khi), (qhi,klo)
        float s[8][4];
#pragma unroll
        for (int i = 0; i < 8; ++i)
#pragma unroll
            for (int j = 0; j < 4; ++j) s[i][j] = 0.0f;

#pragma unroll
        for (int term = 0; term < 3; ++term) {
#pragma unroll
            for (int i = 0; i < 4; ++i) {
                int qc = (term == 1) ? i + 4 : i;
                int kc = (term == 2) ? i + 4 : i;
                uint32_t qa[4];
                ldsm4(qa, sbQ + ((wid * 16 + lrow) * STR + qc * 16 + lcol) * 2);
#pragma unroll
                for (int nb = 0; nb < 4; ++nb) {
                    uint32_t r[4];
                    ldsm4(r, kbase + ((nb * 16 + lrow) * STR + kc * 16 + lcol) * 2);
                    mma16816(s[nb * 2],     qa, r[0], r[2]);
                    mma16816(s[nb * 2 + 1], qa, r[1], r[3]);
                }
            }
        }

        // ---- scale + causal mask (only last two tiles can touch diagonal)
        const bool diag = (t >= ntiles - 2);
#pragma unroll
        for (int nt = 0; nt < 8; ++nt)
#pragma unroll
            for (int ee = 0; ee < 4; ++ee) {
                int col = k0 + nt * 8 + tg * 2 + (ee & 1);
                int row = (ee < 2) ? rowg0 : rowg1;
                if (diag && col > row) s[nt][ee] = -1e30f;
                else                   s[nt][ee] *= 0.125f;
            }

        // ---- online softmax (quad reductions)
        float rmax0 = -1e30f, rmax1 = -1e30f;
#pragma unroll
        for (int nt = 0; nt < 8; ++nt) {
            rmax0 = fmaxf(rmax0, fmaxf(s[nt][0], s[nt][1]));
            rmax1 = fmaxf(rmax1, fmaxf(s[nt][2], s[nt][3]));
        }
        rmax0 = fmaxf(rmax0, __shfl_xor_sync(0xffffffffu, rmax0, 1));
        rmax0 = fmaxf(rmax0, __shfl_xor_sync(0xffffffffu, rmax0, 2));
        rmax1 = fmaxf(rmax1, __shfl_xor_sync(0xffffffffu, rmax1, 1));
        rmax1 = fmaxf(rmax1, __shfl_xor_sync(0xffffffffu, rmax1, 2));

        float mn0 = fmaxf(m0, rmax0), mn1 = fmaxf(m1, rmax1);
        float al0 = __expf(m0 - mn0), al1 = __expf(m1 - mn1);
        m0 = mn0; m1 = mn1;

        float rs0 = 0.0f, rs1 = 0.0f;
#pragma unroll
        for (int nt = 0; nt < 8; ++nt) {
            s[nt][0] = __expf(s[nt][0] - m0);
            s[nt][1] = __expf(s[nt][1] - m0);
            s[nt][2] = __expf(s[nt][2] - m1);
            s[nt][3] = __expf(s[nt][3] - m1);
            rs0 += s[nt][0] + s[nt][1];
            rs1 += s[nt][2] + s[nt][3];
        }
        rs0 += __shfl_xor_sync(0xffffffffu, rs0, 1);
        rs0 += __shfl_xor_sync(0xffffffffu, rs0, 2);
        rs1 += __shfl_xor_sync(0xffffffffu, rs1, 1);
        rs1 += __shfl_xor_sync(0xffffffffu, rs1, 2);
        l0 = l0 * al0 + rs0;
        l1 = l1 * al1 + rs1;
#pragma unroll
        for (int nt = 0; nt < 8; ++nt) {
            o[nt][0] *= al0; o[nt][1] *= al0;
            o[nt][2] *= al1; o[nt][3] *= al1;
        }

        // ---- P -> bf16 hi/lo A-fragments, straight from S fragments
        uint32_t ph[4][4], pl[4][4];
#pragma unroll
        for (int kc = 0; kc < 4; ++kc) {
            const float* se = s[kc * 2];
            const float* so = s[kc * 2 + 1];
            __nv_bfloat16 he0 = __float2bfloat16(se[0]), he1 = __float2bfloat16(se[1]);
            __nv_bfloat16 he2 = __float2bfloat16(se[2]), he3 = __float2bfloat16(se[3]);
            __nv_bfloat16 ho0 = __float2bfloat16(so[0]), ho1 = __float2bfloat16(so[1]);
            __nv_bfloat16 ho2 = __float2bfloat16(so[2]), ho3 = __float2bfloat16(so[3]);
            ph[kc][0] = pk(he0, he1); ph[kc][1] = pk(he2, he3);
            ph[kc][2] = pk(ho0, ho1); ph[kc][3] = pk(ho2, ho3);
            pl[kc][0] = pkf(se[0] - __bfloat162float(he0), se[1] - __bfloat162float(he1));
            pl[kc][1] = pkf(se[2] - __bfloat162float(he2), se[3] - __bfloat162float(he3));
            pl[kc][2] = pkf(so[0] - __bfloat162float(ho0), so[1] - __bfloat162float(ho1));
            pl[kc][3] = pkf(so[2] - __bfloat162float(ho2), so[3] - __bfloat162float(ho3));
        }

        // ---- O += Ph*Vh + Pl*Vh + Ph*Vl   (V via ldmatrix.trans)
#pragma unroll
        for (int kc = 0; kc < 4; ++kc) {
#pragma unroll
            for (int db = 0; db < 4; ++db) {
                uint32_t rh[4];
                ldsm4t(rh, vbase + ((kc * 16 + lrow) * STR + db * 16 + lcol) * 2);
                mma16816(o[db * 2],     ph[kc], rh[0], rh[1]);
                mma16816(o[db * 2 + 1], ph[kc], rh[2], rh[3]);
                mma16816(o[db * 2],     pl[kc], rh[0], rh[1]);
                mma16816(o[db * 2 + 1], pl[kc], rh[2], rh[3]);
                uint32_t rl[4];
                ldsm4t(rl, vbase + ((kc * 16 + lrow) * STR + 64 + db * 16 + lcol) * 2);
                mma16816(o[db * 2],     ph[kc], rl[0], rl[1]);
                mma16816(o[db * 2 + 1], ph[kc], rl[2], rl[3]);
            }
        }
    }

    // ---- epilogue: write E' split [hi|lo|hi] to Eo [4096, 3072]
    float inv0 = 1.0f / l0, inv1 = 1.0f / l1;
    size_t r0 = (size_t)(b * 2048) + rowg0;
    size_t r1 = (size_t)(b * 2048) + rowg1;
#pragma unroll
    for (int nt = 0; nt < 8; ++nt) {
        int col = h * 64 + nt * 8 + tg * 2;
        float a0 = o[nt][0] * inv0, a1 = o[nt][1] * inv0;
        float b0 = o[nt][2] * inv1, b1 = o[nt][3] * inv1;
        __nv_bfloat16 ah0 = __float2bfloat16(a0), ah1 = __float2bfloat16(a1);
        __nv_bfloat16 bh0 = __float2bfloat16(b0), bh1 = __float2bfloat16(b1);
        uint32_t ahi = pk(ah0, ah1);
        uint32_t alo = pkf(a0 - __bfloat162float(ah0), a1 - __bfloat162float(ah1));
        uint32_t bhi = pk(bh0, bh1);
        uint32_t blo = pkf(b0 - __bfloat162float(bh0), b1 - __bfloat162float(bh1));
        __nv_bfloat16* p0 = Eo + r0 * K3 + col;
        __nv_bfloat16* p1 = Eo + r1 * K3 + col;
        *(uint32_t*)(p0)        = ahi;
        *(uint32_t*)(p0 + 1024) = alo;
        *(uint32_t*)(p0 + 2048) = ahi;
        *(uint32_t*)(p1)        = bhi;
        *(uint32_t*)(p1 + 1024) = blo;
        *(uint32_t*)(p1 + 2048) = bhi;
    }
}

// ---------------------------------------------------------------------------
// launch
// ---------------------------------------------------------------------------
extern "C" void kernel_launch(void* const* d_in, const int* in_sizes, int n_in,
                              void* d_out, int out_size) {
    (void)in_sizes; (void)n_in; (void)out_size;
    const float* x    = (const float*)d_in[0];
    const float* wqkv = (const float*)d_in[1];
    const float* w0   = (const float*)d_in[2];
    float* out = (float*)d_out;

    __nv_bfloat16 *a2, *w2, *qd, *kd, *vd;
    cudaGetSymbolAddress((void**)&a2, g_a2);
    cudaGetSymbolAddress((void**)&w2, g_w2);
    cudaGetSymbolAddress((void**)&qd, g_q);
    cudaGetSymbolAddress((void**)&kd, g_k);
    cudaGetSymbolAddress((void**)&vd, g_v);

    cudaFuncSetAttribute(gemm_mma,
                         cudaFuncAttributeMaxDynamicSharedMemorySize, GEMM_SMEM);
    cudaFuncSetAttribute(attn_mma3,
                         cudaFuncAttributeMaxDynamicSharedMemorySize, ATT_SMEM);

    const int M = 4096;

    split3_kernel<<<(M * E_DIM / 4 + 255) / 256, 256>>>(x, a2, M, E_DIM, 1);
    split3_kernel<<<(3 * E_DIM * E_DIM / 4 + 255) / 256, 256>>>(wqkv, w2, 3 * E_DIM, E_DIM, 2);

    // gemm1: QKV, fused split epilogue -> Q'/K'/V' compact
    gemm_mma<<<dim3(3 * E_DIM / BN, M / BM), 256, GEMM_SMEM>>>(
        a2, w2, nullptr, M, 3 * E_DIM, K3, 1, qd, kd, vd);

    // attention -> E' (into g_a2)
    attn_mma3<<<dim3(S_LEN / 128, 16, 2), 256, ATT_SMEM>>>(qd, kd, vd, a2);

    split3_kernel<<<(E_DIM * E_DIM / 4 + 255) / 256, 256>>>(w0, w2, E_DIM, E_DIM, 2);

    // gemm2: out projection, fp32 epilogue
    gemm_mma<<<dim3(E_DIM / BN, M / BM), 256, GEMM_SMEM>>>(
        a2, w2, out, M, E_DIM, K3, 0, nullptr, nullptr, nullptr);
}

// round 9
// speedup vs baseline: 1.0954x; 1.0954x over previous
#include <cuda_runtime.h>
#include <cuda_bf16.h>
#include <cstdint>
#include <cstddef>

// ---------------------------------------------------------------------------
// MHA: B=2, S=2048, E=1024, H=16, D=64, fp32, causal. mma.sync bf16 split-hi/lo.
//  split3(x)->A', split3(wqkv)->B'
//  gemm1 (fused epi): Q'/K'/V' compact [hi(64)|lo(64)] bf16, per (b,h)
//  attn: BR=128 paired q-tiles (perfect causal balance, 1 wave),
//        double-buffered K/V, 3-term chunk-paired QK -> E' [hi|lo|hi]
//  split3(w0)->B' ; gemm2 -> fp32 out
// ---------------------------------------------------------------------------

#define S_LEN   2048
#define E_DIM   1024
#define K3      3072

__device__ __nv_bfloat16 g_a2[4096 * K3];            // X' then E'
__device__ __nv_bfloat16 g_w2[3072 * K3];            // Wqkv' then W0'
__device__ __nv_bfloat16 g_q [32 * 2048 * 128];      // Q' [hi|lo]
__device__ __nv_bfloat16 g_k [32 * 2048 * 128];      // K' [hi|lo]
__device__ __nv_bfloat16 g_v [32 * 2048 * 128];      // V' [hi|lo]

// ---------------------------------------------------------------------------
__device__ __forceinline__ uint32_t smem_u32(const void* p) {
    uint32_t a;
    asm("{ .reg .u64 t; cvta.to.shared.u64 t, %1; cvt.u32.u64 %0, t; }"
        : "=r"(a) : "l"(p));
    return a;
}
__device__ __forceinline__ uint32_t pk(__nv_bfloat16 a, __nv_bfloat16 b) {
    __nv_bfloat162 t = __halves2bfloat162(a, b);
    return *reinterpret_cast<uint32_t*>(&t);
}
__device__ __forceinline__ uint32_t pkf(float a, float b) {
    return pk(__float2bfloat16(a), __float2bfloat16(b));
}
__device__ __forceinline__ void ldsm4(uint32_t r[4], uint32_t addr) {
    asm volatile("ldmatrix.sync.aligned.m8n8.x4.shared.b16 {%0,%1,%2,%3}, [%4];"
                 : "=r"(r[0]), "=r"(r[1]), "=r"(r[2]), "=r"(r[3]) : "r"(addr));
}
__device__ __forceinline__ void ldsm4t(uint32_t r[4], uint32_t addr) {
    asm volatile("ldmatrix.sync.aligned.m8n8.x4.trans.shared.b16 {%0,%1,%2,%3}, [%4];"
                 : "=r"(r[0]), "=r"(r[1]), "=r"(r[2]), "=r"(r[3]) : "r"(addr));
}
__device__ __forceinline__ void mma16816(float c[4], const uint32_t a[4],
                                         uint32_t b0, uint32_t b1) {
    asm volatile("mma.sync.aligned.m16n8k16.row.col.f32.bf16.bf16.f32 "
                 "{%0,%1,%2,%3}, {%4,%5,%6,%7}, {%8,%9}, {%0,%1,%2,%3};"
                 : "+f"(c[0]), "+f"(c[1]), "+f"(c[2]), "+f"(c[3])
                 : "r"(a[0]), "r"(a[1]), "r"(a[2]), "r"(a[3]), "r"(b0), "r"(b1));
}
__device__ __forceinline__ void cpa16(uint32_t dst, const void* src) {
    asm volatile("cp.async.cg.shared.global [%0], [%1], 16;" :: "r"(dst), "l"(src));
}

// ---------------------------------------------------------------------------
// split3: fp32 [rows,K] -> bf16 [rows,3K]. loblk 1: [hi|lo|hi]; 2: [hi|hi|lo]
// ---------------------------------------------------------------------------
__global__ void split3_kernel(const float* __restrict__ src,
                              __nv_bfloat16* __restrict__ dst,
                              int rows, int K, int loblk) {
    int t = blockIdx.x * blockDim.x + threadIdx.x;
    int per4 = K >> 2;
    if (t >= rows * per4) return;
    int r = t / per4, c4 = (t - r * per4) * 4;
    float4 v = ((const float4*)src)[t];

    __nv_bfloat16 h0 = __float2bfloat16(v.x), h1 = __float2bfloat16(v.y);
    __nv_bfloat16 h2 = __float2bfloat16(v.z), h3 = __float2bfloat16(v.w);
    uint2 hp = make_uint2(pk(h0, h1), pk(h2, h3));
    uint2 lp = make_uint2(pkf(v.x - __bfloat162float(h0), v.y - __bfloat162float(h1)),
                          pkf(v.z - __bfloat162float(h2), v.w - __bfloat162float(h3)));

    __nv_bfloat16* d0 = dst + (size_t)r * (3 * K) + c4;
    *(uint2*)(d0)         = hp;
    *(uint2*)(d0 + K)     = (loblk == 1) ? lp : hp;
    *(uint2*)(d0 + 2 * K) = (loblk == 1) ? hp : lp;
}

// ---------------------------------------------------------------------------
// GEMM: C = A[M,K] @ B[N,K]^T. 128x128 tile, BK=64, 3-stage cp.async, 1 sync.
// mode 0: fp32 C.  mode 1: fused QKV split epilogue -> Qd/Kd/Vd [hi|lo].
// ---------------------------------------------------------------------------
#define BM 128
#define BN 128
#define BK 64
#define KSTRB 144                       // bytes per smem row (72 bf16, odd 16B)
#define STG_BYTES ((BM + BN) * KSTRB)   // 36864
#define GEMM_SMEM (3 * STG_BYTES)       // 110592

extern __shared__ char sh_raw[];

__global__ __launch_bounds__(256, 2)
void gemm_mma(const __nv_bfloat16* __restrict__ A,
              const __nv_bfloat16* __restrict__ B,
              float* __restrict__ C, int M, int N, int K, int mode,
              __nv_bfloat16* __restrict__ Qd,
              __nv_bfloat16* __restrict__ Kd,
              __nv_bfloat16* __restrict__ Vd) {
    const uint32_t sb = smem_u32(sh_raw);
    const int tid = threadIdx.x, wid = tid >> 5, lane = tid & 31;
    const int bm = blockIdx.y * BM, bn = blockIdx.x * BN;
    const int wm = (wid >> 2) * 64, wn = (wid & 3) * 32;
    const int g = lane >> 2, tg = lane & 3;
    const int lrow = lane & 15, lcol = (lane >> 4) * 8;

    auto load_stage = [&](int s, int kk) {
        uint32_t abase = sb + (uint32_t)s * STG_BYTES;
        uint32_t bbase = abase + BM * KSTRB;
#pragma unroll
        for (int i = 0; i < 8; ++i) {
            int c = tid + i * 256;
            if (c < 1024) {
                int row = c >> 3, k16 = c & 7;
                cpa16(abase + row * KSTRB + k16 * 16,
                      A + (size_t)(bm + row) * K + kk + k16 * 8);
            } else {
                int row = (c - 1024) >> 3, k16 = c & 7;
                cpa16(bbase + row * KSTRB + k16 * 16,
                      B + (size_t)(bn + row) * K + kk + k16 * 8);
            }
        }
        asm volatile("cp.async.commit_group;" ::: "memory");
    };

    float acc[4][4][4];
#pragma unroll
    for (int i = 0; i < 4; ++i)
#pragma unroll
        for (int j = 0; j < 4; ++j)
#pragma unroll
            for (int e = 0; e < 4; ++e) acc[i][j][e] = 0.0f;

    const int NC = K / BK;   // 48
    load_stage(0, 0);
    load_stage(1, BK);

    int st = 0;
    for (int c = 0; c < NC; ++c) {
        if (c + 1 < NC) asm volatile("cp.async.wait_group 1;" ::: "memory");
        else            asm volatile("cp.async.wait_group 0;" ::: "memory");
        __syncthreads();
        if (c + 2 < NC) {
            int ns = st + 2; if (ns >= 3) ns -= 3;
            load_stage(ns, (c + 2) * BK);
        }

        uint32_t abase = sb + (uint32_t)st * STG_BYTES;
        uint32_t bbase = abase + BM * KSTRB;
#pragma unroll
        for (int ks = 0; ks < 4; ++ks) {
            uint32_t a[4][4];
#pragma unroll
            for (int mt = 0; mt < 4; ++mt)
                ldsm4(a[mt], abase + (wm + mt * 16 + lrow) * KSTRB + (ks * 16 + lcol) * 2);
            uint32_t bf[4][2];
#pragma unroll
            for (int nb = 0; nb < 2; ++nb) {
                uint32_t r[4];
                ldsm4(r, bbase + (wn + nb * 16 + lrow) * KSTRB + (ks * 16 + lcol) * 2);
                bf[nb * 2][0] = r[0];     bf[nb * 2][1] = r[2];
                bf[nb * 2 + 1][0] = r[1]; bf[nb * 2 + 1][1] = r[3];
            }
#pragma unroll
            for (int mt = 0; mt < 4; ++mt)
#pragma unroll
                for (int nt = 0; nt < 4; ++nt)
                    mma16816(acc[mt][nt], a[mt], bf[nt][0], bf[nt][1]);
        }
        ++st; if (st >= 3) st = 0;
    }

    if (mode == 0) {
#pragma unroll
        for (int mt = 0; mt < 4; ++mt) {
            int r0 = bm + wm + mt * 16 + g;
#pragma unroll
            for (int nt = 0; nt < 4; ++nt) {
                int col = bn + wn + nt * 8 + tg * 2;
                *(float2*)(C + (size_t)r0 * N + col) =
                    make_float2(acc[mt][nt][0], acc[mt][nt][1]);
                *(float2*)(C + (size_t)(r0 + 8) * N + col) =
                    make_float2(acc[mt][nt][2], acc[mt][nt][3]);
            }
        }
    } else {
        // fused QKV split epilogue: [hi(64)|lo(64)] rows of 128 per (b,h)
#pragma unroll
        for (int nt = 0; nt < 4; ++nt) {
            int cbase = bn + wn + nt * 8 + tg * 2;
            int plane = cbase >> 10, rem = cbase & 1023;
            int h = rem >> 6, d = rem & 63;
            __nv_bfloat16* basep = (plane == 0) ? Qd : (plane == 1) ? Kd : Vd;
#pragma unroll
            for (int mt = 0; mt < 4; ++mt) {
#pragma unroll
                for (int rr = 0; rr < 2; ++rr) {
                    int row = bm + wm + mt * 16 + g + rr * 8;
                    int b = row >> 11, s = row & 2047;
                    float v0 = acc[mt][nt][rr * 2], v1 = acc[mt][nt][rr * 2 + 1];
                    __nv_bfloat16 h0 = __float2bfloat16(v0), h1 = __float2bfloat16(v1);
                    uint32_t hi = pk(h0, h1);
                    uint32_t lo = pkf(v0 - __bfloat162float(h0), v1 - __bfloat162float(h1));
                    __nv_bfloat16* p = basep +
                        ((size_t)(b * 16 + h) * 2048 + s) * 128 + d;
                    *(uint32_t*)(p)      = hi;
                    *(uint32_t*)(p + 64) = lo;
                }
            }
        }
    }
}

// ---------------------------------------------------------------------------
// Flash attention v4: paired q-tiles (qi = 15-x then x) for perfect causal
// balance; 256 CTAs = one wave. BR=128, BC=64, 256 threads, double-buffered
// K/V. Q/K/V compact [hi|lo]; 3-term chunk-paired QK. exp2-domain softmax.
// Writes E' split [hi|lo|hi] to g_a2.
// ---------------------------------------------------------------------------
#define STR 136   // smem stride (elements), odd multiple of 8
#define Q_EL  (128 * STR)
#define KV_EL (64 * STR)
#define ATT_SMEM ((Q_EL + 4 * KV_EL) * 2)   // 104448 B

__global__ __launch_bounds__(256, 2)
void attn_mma4(const __nv_bfloat16* __restrict__ Qg,
               const __nv_bfloat16* __restrict__ Kg,
               const __nv_bfloat16* __restrict__ Vg,
               __nv_bfloat16* __restrict__ Eo) {
    const uint32_t sbQ = smem_u32(sh_raw);

    const int tid = threadIdx.x, wid = tid >> 5, lane = tid & 31;
    const int h = blockIdx.y, b = blockIdx.z;
    const size_t bh = (size_t)(b * 16 + h);
    const int g = lane >> 2, tg = lane & 3;
    const int lrow = lane & 15, lcol = (lane >> 4) * 8;
    const float scale = 0.125f * 1.44269504089f;   // fold log2e -> exp2 domain

    auto load_kv = [&](int buf, int k0) {
        uint32_t kb = sbQ + (Q_EL + buf * 2 * KV_EL) * 2;
        uint32_t vb = kb + KV_EL * 2;
        const __nv_bfloat16* kg = Kg + (bh * 2048 + k0) * 128;
        const __nv_bfloat16* vg = Vg + (bh * 2048 + k0) * 128;
#pragma unroll
        for (int i = 0; i < 4; ++i) {
            int c = tid + i * 256;           // 1024 chunks: 64 rows x 16
            int row = c >> 4, cg = c & 15;
            cpa16(kb + (row * STR + cg * 8) * 2, kg + row * 128 + cg * 8);
            cpa16(vb + (row * STR + cg * 8) * 2, vg + row * 128 + cg * 8);
        }
        asm volatile("cp.async.commit_group;" ::: "memory");
    };

#pragma unroll 1
    for (int ph = 0; ph < 2; ++ph) {
        const int qi = ph ? (int)blockIdx.x : 15 - (int)blockIdx.x;  // big first
        const int q0 = qi * 128;
        const int ntiles = 2 * qi + 2;
        const int rowg0 = q0 + wid * 16 + g, rowg1 = rowg0 + 8;

        // prologue: Q tile (128 x 128 -> 2048 chunks) + first K/V tile
        {
            const __nv_bfloat16* qg = Qg + (bh * 2048 + q0) * 128;
#pragma unroll
            for (int i = 0; i < 8; ++i) {
                int c = tid + i * 256;       // 2048 chunks: 128 rows x 16
                int row = c >> 4, cg = c & 15;
                cpa16(sbQ + (row * STR + cg * 8) * 2, qg + row * 128 + cg * 8);
            }
            asm volatile("cp.async.commit_group;" ::: "memory");
        }
        load_kv(0, 0);

        float m0 = -1e30f, m1 = -1e30f, l0 = 0.0f, l1 = 0.0f;
        float o[8][4];
#pragma unroll
        for (int i = 0; i < 8; ++i)
#pragma unroll
            for (int j = 0; j < 4; ++j) o[i][j] = 0.0f;

        for (int t = 0; t < ntiles; ++t) {
            const int k0 = t * 64;
            asm volatile("cp.async.wait_group 0;" ::: "memory");
            __syncthreads();   // tile t visible; all warps done with buf (t+1)&1
            if (t + 1 < ntiles) load_kv((t + 1) & 1, (t + 1) * 64);

            const uint32_t kbase = sbQ + (Q_EL + (t & 1) * 2 * KV_EL) * 2;
            const uint32_t vbase = kbase + KV_EL * 2;

            // ---- S = 3-term QK^T: (qhi,khi), (qlo,khi), (qhi,klo)
            float s[8][4];
#pragma unroll
            for (int i = 0; i < 8; ++i)
#pragma unroll
                for (int j = 0; j < 4; ++j) s[i][j] = 0.0f;

#pragma unroll
            for (int term = 0; term < 3; ++term) {
#pragma unroll
                for (int i = 0; i < 4; ++i) {
                    int qc = (term == 1) ? i + 4 : i;
                    int kc = (term == 2) ? i + 4 : i;
                    uint32_t qa[4];
                    ldsm4(qa, sbQ + ((wid * 16 + lrow) * STR + qc * 16 + lcol) * 2);
#pragma unroll
                    for (int nb = 0; nb < 4; ++nb) {
                        uint32_t r[4];
                        ldsm4(r, kbase + ((nb * 16 + lrow) * STR + kc * 16 + lcol) * 2);
                        mma16816(s[nb * 2],     qa, r[0], r[2]);
                        mma16816(s[nb * 2 + 1], qa, r[1], r[3]);
                    }
                }
            }

            // ---- scale (exp2 domain) + causal mask
            const bool diag = (t >= ntiles - 2);
#pragma unroll
            for (int nt = 0; nt < 8; ++nt)
#pragma unroll
                for (int ee = 0; ee < 4; ++ee) {
                    int col = k0 + nt * 8 + tg * 2 + (ee & 1);
                    int row = (ee < 2) ? rowg0 : rowg1;
                    if (diag && col > row) s[nt][ee] = -1e30f;
                    else                   s[nt][ee] *= scale;
                }

            // ---- online softmax (quad reductions, exp2 domain)
            float rmax0 = -1e30f, rmax1 = -1e30f;
#pragma unroll
            for (int nt = 0; nt < 8; ++nt) {
                rmax0 = fmaxf(rmax0, fmaxf(s[nt][0], s[nt][1]));
                rmax1 = fmaxf(rmax1, fmaxf(s[nt][2], s[nt][3]));
            }
            rmax0 = fmaxf(rmax0, __shfl_xor_sync(0xffffffffu, rmax0, 1));
            rmax0 = fmaxf(rmax0, __shfl_xor_sync(0xffffffffu, rmax0, 2));
            rmax1 = fmaxf(rmax1, __shfl_xor_sync(0xffffffffu, rmax1, 1));
            rmax1 = fmaxf(rmax1, __shfl_xor_sync(0xffffffffu, rmax1, 2));

            float mn0 = fmaxf(m0, rmax0), mn1 = fmaxf(m1, rmax1);
            float al0 = exp2f(m0 - mn0), al1 = exp2f(m1 - mn1);
            m0 = mn0; m1 = mn1;

            float rs0 = 0.0f, rs1 = 0.0f;
#pragma unroll
            for (int nt = 0; nt < 8; ++nt) {
                s[nt][0] = exp2f(s[nt][0] - m0);
                s[nt][1] = exp2f(s[nt][1] - m0);
                s[nt][2] = exp2f(s[nt][2] - m1);
                s[nt][3] = exp2f(s[nt][3] - m1);
                rs0 += s[nt][0] + s[nt][1];
                rs1 += s[nt][2] + s[nt][3];
            }
            rs0 += __shfl_xor_sync(0xffffffffu, rs0, 1);
            rs0 += __shfl_xor_sync(0xffffffffu, rs0, 2);
            rs1 += __shfl_xor_sync(0xffffffffu, rs1, 1);
            rs1 += __shfl_xor_sync(0xffffffffu, rs1, 2);
            l0 = l0 * al0 + rs0;
            l1 = l1 * al1 + rs1;
#pragma unroll
            for (int nt = 0; nt < 8; ++nt) {
                o[nt][0] *= al0; o[nt][1] *= al0;
                o[nt][2] *= al1; o[nt][3] *= al1;
            }

            // ---- P -> bf16 hi/lo A-fragments, straight from S fragments
            uint32_t pfh[4][4], pfl[4][4];
#pragma unroll
            for (int kc = 0; kc < 4; ++kc) {
                const float* se = s[kc * 2];
                const float* so = s[kc * 2 + 1];
                __nv_bfloat16 he0 = __float2bfloat16(se[0]), he1 = __float2bfloat16(se[1]);
                __nv_bfloat16 he2 = __float2bfloat16(se[2]), he3 = __float2bfloat16(se[3]);
                __nv_bfloat16 ho0 = __float2bfloat16(so[0]), ho1 = __float2bfloat16(so[1]);
                __nv_bfloat16 ho2 = __float2bfloat16(so[2]), ho3 = __float2bfloat16(so[3]);
                pfh[kc][0] = pk(he0, he1); pfh[kc][1] = pk(he2, he3);
                pfh[kc][2] = pk(ho0, ho1); pfh[kc][3] = pk(ho2, ho3);
                pfl[kc][0] = pkf(se[0] - __bfloat162float(he0), se[1] - __bfloat162float(he1));
                pfl[kc][1] = pkf(se[2] - __bfloat162float(he2), se[3] - __bfloat162float(he3));
                pfl[kc][2] = pkf(so[0] - __bfloat162float(ho0), so[1] - __bfloat162float(ho1));
                pfl[kc][3] = pkf(so[2] - __bfloat162float(ho2), so[3] - __bfloat162float(ho3));
            }

            // ---- O += Ph*Vh + Pl*Vh + Ph*Vl   (V via ldmatrix.trans)
#pragma unroll
            for (int kc = 0; kc < 4; ++kc) {
#pragma unroll
                for (int db = 0; db < 4; ++db) {
                    uint32_t rh[4];
                    ldsm4t(rh, vbase + ((kc * 16 + lrow) * STR + db * 16 + lcol) * 2);
                    mma16816(o[db * 2],     pfh[kc], rh[0], rh[1]);
                    mma16816(o[db * 2 + 1], pfh[kc], rh[2], rh[3]);
                    mma16816(o[db * 2],     pfl[kc], rh[0], rh[1]);
                    mma16816(o[db * 2 + 1], pfl[kc], rh[2], rh[3]);
                    uint32_t rl[4];
                    ldsm4t(rl, vbase + ((kc * 16 + lrow) * STR + 64 + db * 16 + lcol) * 2);
                    mma16816(o[db * 2],     pfh[kc], rl[0], rl[1]);
                    mma16816(o[db * 2 + 1], pfh[kc], rl[2], rl[3]);
                }
            }
        }

        // ---- epilogue: write E' split [hi|lo|hi] to Eo [4096, 3072]
        float inv0 = 1.0f / l0, inv1 = 1.0f / l1;
        size_t r0 = (size_t)(b * 2048) + rowg0;
        size_t r1 = (size_t)(b * 2048) + rowg1;
#pragma unroll
        for (int nt = 0; nt < 8; ++nt) {
            int col = h * 64 + nt * 8 + tg * 2;
            float a0 = o[nt][0] * inv0, a1 = o[nt][1] * inv0;
            float b0 = o[nt][2] * inv1, b1 = o[nt][3] * inv1;
            __nv_bfloat16 ah0 = __float2bfloat16(a0), ah1 = __float2bfloat16(a1);
            __nv_bfloat16 bh0 = __float2bfloat16(b0), bh1 = __float2bfloat16(b1);
            uint32_t ahi = pk(ah0, ah1);
            uint32_t alo = pkf(a0 - __bfloat162float(ah0), a1 - __bfloat162float(ah1));
            uint32_t bhi = pk(bh0, bh1);
            uint32_t blo = pkf(b0 - __bfloat162float(bh0), b1 - __bfloat162float(bh1));
            __nv_bfloat16* p0 = Eo + r0 * K3 + col;
            __nv_bfloat16* p1 = Eo + r1 * K3 + col;
            *(uint32_t*)(p0)        = ahi;
            *(uint32_t*)(p0 + 1024) = alo;
            *(uint32_t*)(p0 + 2048) = ahi;
            *(uint32_t*)(p1)        = bhi;
            *(uint32_t*)(p1 + 1024) = blo;
            *(uint32_t*)(p1 + 2048) = bhi;
        }

        __syncthreads();   // protect Q/K/V smem before next phase overwrites
    }
}

// ---------------------------------------------------------------------------
// launch
// ---------------------------------------------------------------------------
extern "C" void kernel_launch(void* const* d_in, const int* in_sizes, int n_in,
                              void* d_out, int out_size) {
    (void)in_sizes; (void)n_in; (void)out_size;
    const float* x    = (const float*)d_in[0];
    const float* wqkv = (const float*)d_in[1];
    const float* w0   = (const float*)d_in[2];
    float* out = (float*)d_out;

    __nv_bfloat16 *a2, *w2, *qd, *kd, *vd;
    cudaGetSymbolAddress((void**)&a2, g_a2);
    cudaGetSymbolAddress((void**)&w2, g_w2);
    cudaGetSymbolAddress((void**)&qd, g_q);
    cudaGetSymbolAddress((void**)&kd, g_k);
    cudaGetSymbolAddress((void**)&vd, g_v);

    cudaFuncSetAttribute(gemm_mma,
                         cudaFuncAttributeMaxDynamicSharedMemorySize, GEMM_SMEM);
    cudaFuncSetAttribute(attn_mma4,
                         cudaFuncAttributeMaxDynamicSharedMemorySize, ATT_SMEM);

    const int M = 4096;

    split3_kernel<<<(M * E_DIM / 4 + 255) / 256, 256>>>(x, a2, M, E_DIM, 1);
    split3_kernel<<<(3 * E_DIM * E_DIM / 4 + 255) / 256, 256>>>(wqkv, w2, 3 * E_DIM, E_DIM, 2);

    // gemm1: QKV, fused split epilogue -> Q'/K'/V' compact
    gemm_mma<<<dim3(3 * E_DIM / BN, M / BM), 256, GEMM_SMEM>>>(
        a2, w2, nullptr, M, 3 * E_DIM, K3, 1, qd, kd, vd);

    // attention -> E' (into g_a2); paired q-tiles: grid.x = 8
    attn_mma4<<<dim3(8, 16, 2), 256, ATT_SMEM>>>(qd, kd, vd, a2);

    split3_kernel<<<(E_DIM * E_DIM / 4 + 255) / 256, 256>>>(w0, w2, E_DIM, E_DIM, 2);

    // gemm2: out projection, fp32 epilogue
    gemm_mma<<<dim3(E_DIM / BN, M / BM), 256, GEMM_SMEM>>>(
        a2, w2, out, M, E_DIM, K3, 0, nullptr, nullptr, nullptr);
}

// round 10
// speedup vs baseline: 1.1108x; 1.0140x over previous
#include <cuda_runtime.h>
#include <cuda_bf16.h>
#include <cstdint>
#include <cstddef>

// ---------------------------------------------------------------------------
// MHA: B=2, S=2048, E=1024, H=16, D=64, fp32, causal. mma.sync bf16 split-hi/lo.
//  split3(x)->A', split3(wqkv)->B'
//  gemm1 (fused epi): Q'/K'/V' compact [hi(64)|lo(64)] bf16, per (b,h)
//  attn: BR=128 paired q-tiles, double-buffered K/V, fragment-reuse 3-term QK,
//        diag fast-path -> E' [hi|lo|hi]
//  split3(w0)->B' ; gemm2 -> fp32 out
// ---------------------------------------------------------------------------

#define S_LEN   2048
#define E_DIM   1024
#define K3      3072

__device__ __nv_bfloat16 g_a2[4096 * K3];            // X' then E'
__device__ __nv_bfloat16 g_w2[3072 * K3];            // Wqkv' then W0'
__device__ __nv_bfloat16 g_q [32 * 2048 * 128];      // Q' [hi|lo]
__device__ __nv_bfloat16 g_k [32 * 2048 * 128];      // K' [hi|lo]
__device__ __nv_bfloat16 g_v [32 * 2048 * 128];      // V' [hi|lo]

// ---------------------------------------------------------------------------
__device__ __forceinline__ uint32_t smem_u32(const void* p) {
    uint32_t a;
    asm("{ .reg .u64 t; cvta.to.shared.u64 t, %1; cvt.u32.u64 %0, t; }"
        : "=r"(a) : "l"(p));
    return a;
}
__device__ __forceinline__ uint32_t pk(__nv_bfloat16 a, __nv_bfloat16 b) {
    __nv_bfloat162 t = __halves2bfloat162(a, b);
    return *reinterpret_cast<uint32_t*>(&t);
}
__device__ __forceinline__ uint32_t pkf(float a, float b) {
    return pk(__float2bfloat16(a), __float2bfloat16(b));
}
__device__ __forceinline__ void ldsm4(uint32_t r[4], uint32_t addr) {
    asm volatile("ldmatrix.sync.aligned.m8n8.x4.shared.b16 {%0,%1,%2,%3}, [%4];"
                 : "=r"(r[0]), "=r"(r[1]), "=r"(r[2]), "=r"(r[3]) : "r"(addr));
}
__device__ __forceinline__ void ldsm4t(uint32_t r[4], uint32_t addr) {
    asm volatile("ldmatrix.sync.aligned.m8n8.x4.trans.shared.b16 {%0,%1,%2,%3}, [%4];"
                 : "=r"(r[0]), "=r"(r[1]), "=r"(r[2]), "=r"(r[3]) : "r"(addr));
}
__device__ __forceinline__ void mma16816(float c[4], const uint32_t a[4],
                                         uint32_t b0, uint32_t b1) {
    asm volatile("mma.sync.aligned.m16n8k16.row.col.f32.bf16.bf16.f32 "
                 "{%0,%1,%2,%3}, {%4,%5,%6,%7}, {%8,%9}, {%0,%1,%2,%3};"
                 : "+f"(c[0]), "+f"(c[1]), "+f"(c[2]), "+f"(c[3])
                 : "r"(a[0]), "r"(a[1]), "r"(a[2]), "r"(a[3]), "r"(b0), "r"(b1));
}
__device__ __forceinline__ void cpa16(uint32_t dst, const void* src) {
    asm volatile("cp.async.cg.shared.global [%0], [%1], 16;" :: "r"(dst), "l"(src));
}

// ---------------------------------------------------------------------------
// split3: fp32 [rows,K] -> bf16 [rows,3K]. loblk 1: [hi|lo|hi]; 2: [hi|hi|lo]
// ---------------------------------------------------------------------------
__global__ void split3_kernel(const float* __restrict__ src,
                              __nv_bfloat16* __restrict__ dst,
                              int rows, int K, int loblk) {
    int t = blockIdx.x * blockDim.x + threadIdx.x;
    int per4 = K >> 2;
    if (t >= rows * per4) return;
    int r = t / per4, c4 = (t - r * per4) * 4;
    float4 v = ((const float4*)src)[t];

    __nv_bfloat16 h0 = __float2bfloat16(v.x), h1 = __float2bfloat16(v.y);
    __nv_bfloat16 h2 = __float2bfloat16(v.z), h3 = __float2bfloat16(v.w);
    uint2 hp = make_uint2(pk(h0, h1), pk(h2, h3));
    uint2 lp = make_uint2(pkf(v.x - __bfloat162float(h0), v.y - __bfloat162float(h1)),
                          pkf(v.z - __bfloat162float(h2), v.w - __bfloat162float(h3)));

    __nv_bfloat16* d0 = dst + (size_t)r * (3 * K) + c4;
    *(uint2*)(d0)         = hp;
    *(uint2*)(d0 + K)     = (loblk == 1) ? lp : hp;
    *(uint2*)(d0 + 2 * K) = (loblk == 1) ? hp : lp;
}

// ---------------------------------------------------------------------------
// GEMM: C = A[M,K] @ B[N,K]^T. 128x128 tile, BK=64, 3-stage cp.async, 1 sync.
// mode 0: fp32 C.  mode 1: fused QKV split epilogue -> Qd/Kd/Vd [hi|lo].
// ---------------------------------------------------------------------------
#define BM 128
#define BN 128
#define BK 64
#define KSTRB 144                       // bytes per smem row (72 bf16, odd 16B)
#define STG_BYTES ((BM + BN) * KSTRB)   // 36864
#define GEMM_SMEM (3 * STG_BYTES)       // 110592

extern __shared__ char sh_raw[];

__global__ __launch_bounds__(256, 2)
void gemm_mma(const __nv_bfloat16* __restrict__ A,
              const __nv_bfloat16* __restrict__ B,
              float* __restrict__ C, int M, int N, int K, int mode,
              __nv_bfloat16* __restrict__ Qd,
              __nv_bfloat16* __restrict__ Kd,
              __nv_bfloat16* __restrict__ Vd) {
    const uint32_t sb = smem_u32(sh_raw);
    const int tid = threadIdx.x, wid = tid >> 5, lane = tid & 31;
    const int bm = blockIdx.y * BM, bn = blockIdx.x * BN;
    const int wm = (wid >> 2) * 64, wn = (wid & 3) * 32;
    const int g = lane >> 2, tg = lane & 3;
    const int lrow = lane & 15, lcol = (lane >> 4) * 8;

    auto load_stage = [&](int s, int kk) {
        uint32_t abase = sb + (uint32_t)s * STG_BYTES;
        uint32_t bbase = abase + BM * KSTRB;
#pragma unroll
        for (int i = 0; i < 8; ++i) {
            int c = tid + i * 256;
            if (c < 1024) {
                int row = c >> 3, k16 = c & 7;
                cpa16(abase + row * KSTRB + k16 * 16,
                      A + (size_t)(bm + row) * K + kk + k16 * 8);
            } else {
                int row = (c - 1024) >> 3, k16 = c & 7;
                cpa16(bbase + row * KSTRB + k16 * 16,
                      B + (size_t)(bn + row) * K + kk + k16 * 8);
            }
        }
        asm volatile("cp.async.commit_group;" ::: "memory");
    };

    float acc[4][4][4];
#pragma unroll
    for (int i = 0; i < 4; ++i)
#pragma unroll
        for (int j = 0; j < 4; ++j)
#pragma unroll
            for (int e = 0; e < 4; ++e) acc[i][j][e] = 0.0f;

    const int NC = K / BK;   // 48
    load_stage(0, 0);
    load_stage(1, BK);

    int st = 0;
    for (int c = 0; c < NC; ++c) {
        if (c + 1 < NC) asm volatile("cp.async.wait_group 1;" ::: "memory");
        else            asm volatile("cp.async.wait_group 0;" ::: "memory");
        __syncthreads();
        if (c + 2 < NC) {
            int ns = st + 2; if (ns >= 3) ns -= 3;
            load_stage(ns, (c + 2) * BK);
        }

        uint32_t abase = sb + (uint32_t)st * STG_BYTES;
        uint32_t bbase = abase + BM * KSTRB;
#pragma unroll
        for (int ks = 0; ks < 4; ++ks) {
            uint32_t a[4][4];
#pragma unroll
            for (int mt = 0; mt < 4; ++mt)
                ldsm4(a[mt], abase + (wm + mt * 16 + lrow) * KSTRB + (ks * 16 + lcol) * 2);
            uint32_t bf[4][2];
#pragma unroll
            for (int nb = 0; nb < 2; ++nb) {
                uint32_t r[4];
                ldsm4(r, bbase + (wn + nb * 16 + lrow) * KSTRB + (ks * 16 + lcol) * 2);
                bf[nb * 2][0] = r[0];     bf[nb * 2][1] = r[2];
                bf[nb * 2 + 1][0] = r[1]; bf[nb * 2 + 1][1] = r[3];
            }
#pragma unroll
            for (int mt = 0; mt < 4; ++mt)
#pragma unroll
                for (int nt = 0; nt < 4; ++nt)
                    mma16816(acc[mt][nt], a[mt], bf[nt][0], bf[nt][1]);
        }
        ++st; if (st >= 3) st = 0;
    }

    if (mode == 0) {
#pragma unroll
        for (int mt = 0; mt < 4; ++mt) {
            int r0 = bm + wm + mt * 16 + g;
#pragma unroll
            for (int nt = 0; nt < 4; ++nt) {
                int col = bn + wn + nt * 8 + tg * 2;
                *(float2*)(C + (size_t)r0 * N + col) =
                    make_float2(acc[mt][nt][0], acc[mt][nt][1]);
                *(float2*)(C + (size_t)(r0 + 8) * N + col) =
                    make_float2(acc[mt][nt][2], acc[mt][nt][3]);
            }
        }
    } else {
        // fused QKV split epilogue: [hi(64)|lo(64)] rows of 128 per (b,h)
#pragma unroll
        for (int nt = 0; nt < 4; ++nt) {
            int cbase = bn + wn + nt * 8 + tg * 2;
            int plane = cbase >> 10, rem = cbase & 1023;
            int h = rem >> 6, d = rem & 63;
            __nv_bfloat16* basep = (plane == 0) ? Qd : (plane == 1) ? Kd : Vd;
#pragma unroll
            for (int mt = 0; mt < 4; ++mt) {
#pragma unroll
                for (int rr = 0; rr < 2; ++rr) {
                    int row = bm + wm + mt * 16 + g + rr * 8;
                    int b = row >> 11, s = row & 2047;
                    float v0 = acc[mt][nt][rr * 2], v1 = acc[mt][nt][rr * 2 + 1];
                    __nv_bfloat16 h0 = __float2bfloat16(v0), h1 = __float2bfloat16(v1);
                    uint32_t hi = pk(h0, h1);
                    uint32_t lo = pkf(v0 - __bfloat162float(h0), v1 - __bfloat162float(h1));
                    __nv_bfloat16* p = basep +
                        ((size_t)(b * 16 + h) * 2048 + s) * 128 + d;
                    *(uint32_t*)(p)      = hi;
                    *(uint32_t*)(p + 64) = lo;
                }
            }
        }
    }
}

// ---------------------------------------------------------------------------
// Flash attention v5: paired q-tiles (perfect causal balance, 1 wave), BR=128,
// BC=64, double-buffered K/V, fragment-reuse 3-term QK (40 ldsm vs 60),
// diagonal fast-path masking. exp2-domain softmax. E' split [hi|lo|hi].
// ---------------------------------------------------------------------------
#define STR 136   // smem stride (elements), odd multiple of 8
#define Q_EL  (128 * STR)
#define KV_EL (64 * STR)
#define ATT_SMEM ((Q_EL + 4 * KV_EL) * 2)   // 104448 B

__global__ __launch_bounds__(256, 2)
void attn_mma5(const __nv_bfloat16* __restrict__ Qg,
               const __nv_bfloat16* __restrict__ Kg,
               const __nv_bfloat16* __restrict__ Vg,
               __nv_bfloat16* __restrict__ Eo) {
    const uint32_t sbQ = smem_u32(sh_raw);

    const int tid = threadIdx.x, wid = tid >> 5, lane = tid & 31;
    const int h = blockIdx.y, b = blockIdx.z;
    const size_t bh = (size_t)(b * 16 + h);
    const int g = lane >> 2, tg = lane & 3;
    const int lrow = lane & 15, lcol = (lane >> 4) * 8;
    const float scale = 0.125f * 1.44269504089f;   // fold log2e -> exp2 domain

    auto load_kv = [&](int buf, int k0) {
        uint32_t kb = sbQ + (Q_EL + buf * 2 * KV_EL) * 2;
        uint32_t vb = kb + KV_EL * 2;
        const __nv_bfloat16* kg = Kg + (bh * 2048 + k0) * 128;
        const __nv_bfloat16* vg = Vg + (bh * 2048 + k0) * 128;
#pragma unroll
        for (int i = 0; i < 4; ++i) {
            int c = tid + i * 256;           // 1024 chunks: 64 rows x 16
            int row = c >> 4, cg = c & 15;
            cpa16(kb + (row * STR + cg * 8) * 2, kg + row * 128 + cg * 8);
            cpa16(vb + (row * STR + cg * 8) * 2, vg + row * 128 + cg * 8);
        }
        asm volatile("cp.async.commit_group;" ::: "memory");
    };

#pragma unroll 1
    for (int ph = 0; ph < 2; ++ph) {
        const int qi = ph ? (int)blockIdx.x : 15 - (int)blockIdx.x;  // big first
        const int q0 = qi * 128;
        const int ntiles = 2 * qi + 2;
        const int rowg0 = q0 + wid * 16 + g, rowg1 = rowg0 + 8;

        // prologue: Q tile (128 x 128 -> 2048 chunks) + first K/V tile
        {
            const __nv_bfloat16* qg = Qg + (bh * 2048 + q0) * 128;
#pragma unroll
            for (int i = 0; i < 8; ++i) {
                int c = tid + i * 256;       // 2048 chunks: 128 rows x 16
                int row = c >> 4, cg = c & 15;
                cpa16(sbQ + (row * STR + cg * 8) * 2, qg + row * 128 + cg * 8);
            }
            asm volatile("cp.async.commit_group;" ::: "memory");
        }
        load_kv(0, 0);

        float m0 = -1e30f, m1 = -1e30f, l0 = 0.0f, l1 = 0.0f;
        float o[8][4];
#pragma unroll
        for (int i = 0; i < 8; ++i)
#pragma unroll
            for (int j = 0; j < 4; ++j) o[i][j] = 0.0f;

        for (int t = 0; t < ntiles; ++t) {
            const int k0 = t * 64;
            asm volatile("cp.async.wait_group 0;" ::: "memory");
            __syncthreads();   // tile t visible; all warps done with buf (t+1)&1
            if (t + 1 < ntiles) load_kv((t + 1) & 1, (t + 1) * 64);

            const uint32_t kbase = sbQ + (Q_EL + (t & 1) * 2 * KV_EL) * 2;
            const uint32_t vbase = kbase + KV_EL * 2;

            // ---- S = 3-term QK^T with fragment reuse:
            //      per i: load qhi(i), qlo(i+4); per nb: khi(i), klo(i+4);
            //      mma (qhi,khi), (qlo,khi), (qhi,klo)
            float s[8][4];
#pragma unroll
            for (int i = 0; i < 8; ++i)
#pragma unroll
                for (int j = 0; j < 4; ++j) s[i][j] = 0.0f;

#pragma unroll
            for (int i = 0; i < 4; ++i) {
                uint32_t qa0[4], qa1[4];
                ldsm4(qa0, sbQ + ((wid * 16 + lrow) * STR + i * 16 + lcol) * 2);
                ldsm4(qa1, sbQ + ((wid * 16 + lrow) * STR + (i + 4) * 16 + lcol) * 2);
#pragma unroll
                for (int nb = 0; nb < 4; ++nb) {
                    uint32_t r0[4], r1[4];
                    ldsm4(r0, kbase + ((nb * 16 + lrow) * STR + i * 16 + lcol) * 2);
                    ldsm4(r1, kbase + ((nb * 16 + lrow) * STR + (i + 4) * 16 + lcol) * 2);
                    mma16816(s[nb * 2],     qa0, r0[0], r0[2]);
                    mma16816(s[nb * 2 + 1], qa0, r0[1], r0[3]);
                    mma16816(s[nb * 2],     qa1, r0[0], r0[2]);
                    mma16816(s[nb * 2 + 1], qa1, r0[1], r0[3]);
                    mma16816(s[nb * 2],     qa0, r1[0], r1[2]);
                    mma16816(s[nb * 2 + 1], qa0, r1[1], r1[3]);
                }
            }

            // ---- scale (exp2 domain); mask only on diagonal tiles
            if (t >= ntiles - 2) {
#pragma unroll
                for (int nt = 0; nt < 8; ++nt)
#pragma unroll
                    for (int ee = 0; ee < 4; ++ee) {
                        int col = k0 + nt * 8 + tg * 2 + (ee & 1);
                        int row = (ee < 2) ? rowg0 : rowg1;
                        if (col > row) s[nt][ee] = -1e30f;
                        else           s[nt][ee] *= scale;
                    }
            } else {
#pragma unroll
                for (int nt = 0; nt < 8; ++nt)
#pragma unroll
                    for (int ee = 0; ee < 4; ++ee) s[nt][ee] *= scale;
            }

            // ---- online softmax (quad reductions, exp2 domain)
            float rmax0 = -1e30f, rmax1 = -1e30f;
#pragma unroll
            for (int nt = 0; nt < 8; ++nt) {
                rmax0 = fmaxf(rmax0, fmaxf(s[nt][0], s[nt][1]));
                rmax1 = fmaxf(rmax1, fmaxf(s[nt][2], s[nt][3]));
            }
            rmax0 = fmaxf(rmax0, __shfl_xor_sync(0xffffffffu, rmax0, 1));
            rmax0 = fmaxf(rmax0, __shfl_xor_sync(0xffffffffu, rmax0, 2));
            rmax1 = fmaxf(rmax1, __shfl_xor_sync(0xffffffffu, rmax1, 1));
            rmax1 = fmaxf(rmax1, __shfl_xor_sync(0xffffffffu, rmax1, 2));

            float mn0 = fmaxf(m0, rmax0), mn1 = fmaxf(m1, rmax1);
            float al0 = exp2f(m0 - mn0), al1 = exp2f(m1 - mn1);
            m0 = mn0; m1 = mn1;

            float rs0 = 0.0f, rs1 = 0.0f;
#pragma unroll
            for (int nt = 0; nt < 8; ++nt) {
                s[nt][0] = exp2f(s[nt][0] - m0);
                s[nt][1] = exp2f(s[nt][1] - m0);
                s[nt][2] = exp2f(s[nt][2] - m1);
                s[nt][3] = exp2f(s[nt][3] - m1);
                rs0 += s[nt][0] + s[nt][1];
                rs1 += s[nt][2] + s[nt][3];
            }
            rs0 += __shfl_xor_sync(0xffffffffu, rs0, 1);
            rs0 += __shfl_xor_sync(0xffffffffu, rs0, 2);
            rs1 += __shfl_xor_sync(0xffffffffu, rs1, 1);
            rs1 += __shfl_xor_sync(0xffffffffu, rs1, 2);
            l0 = l0 * al0 + rs0;
            l1 = l1 * al1 + rs1;
#pragma unroll
            for (int nt = 0; nt < 8; ++nt) {
                o[nt][0] *= al0; o[nt][1] *= al0;
                o[nt][2] *= al1; o[nt][3] *= al1;
            }

            // ---- P -> bf16 hi/lo A-fragments, straight from S fragments
            uint32_t pfh[4][4], pfl[4][4];
#pragma unroll
            for (int kc = 0; kc < 4; ++kc) {
                const float* se = s[kc * 2];
                const float* so = s[kc * 2 + 1];
                __nv_bfloat16 he0 = __float2bfloat16(se[0]), he1 = __float2bfloat16(se[1]);
                __nv_bfloat16 he2 = __float2bfloat16(se[2]), he3 = __float2bfloat16(se[3]);
                __nv_bfloat16 ho0 = __float2bfloat16(so[0]), ho1 = __float2bfloat16(so[1]);
                __nv_bfloat16 ho2 = __float2bfloat16(so[2]), ho3 = __float2bfloat16(so[3]);
                pfh[kc][0] = pk(he0, he1); pfh[kc][1] = pk(he2, he3);
                pfh[kc][2] = pk(ho0, ho1); pfh[kc][3] = pk(ho2, ho3);
                pfl[kc][0] = pkf(se[0] - __bfloat162float(he0), se[1] - __bfloat162float(he1));
                pfl[kc][1] = pkf(se[2] - __bfloat162float(he2), se[3] - __bfloat162float(he3));
                pfl[kc][2] = pkf(so[0] - __bfloat162float(ho0), so[1] - __bfloat162float(ho1));
                pfl[kc][3] = pkf(so[2] - __bfloat162float(ho2), so[3] - __bfloat162float(ho3));
            }

            // ---- O += Ph*Vh + Pl*Vh + Ph*Vl   (V via ldmatrix.trans)
#pragma unroll
            for (int kc = 0; kc < 4; ++kc) {
#pragma unroll
                for (int db = 0; db < 4; ++db) {
                    uint32_t rh[4];
                    ldsm4t(rh, vbase + ((kc * 16 + lrow) * STR + db * 16 + lcol) * 2);
                    mma16816(o[db * 2],     pfh[kc], rh[0], rh[1]);
                    mma16816(o[db * 2 + 1], pfh[kc], rh[2], rh[3]);
                    mma16816(o[db * 2],     pfl[kc], rh[0], rh[1]);
                    mma16816(o[db * 2 + 1], pfl[kc], rh[2], rh[3]);
                    uint32_t rl[4];
                    ldsm4t(rl, vbase + ((kc * 16 + lrow) * STR + 64 + db * 16 + lcol) * 2);
                    mma16816(o[db * 2],     pfh[kc], rl[0], rl[1]);
                    mma16816(o[db * 2 + 1], pfh[kc], rl[2], rl[3]);
                }
            }
        }

        // ---- epilogue: write E' split [hi|lo|hi] to Eo [4096, 3072]
        float inv0 = 1.0f / l0, inv1 = 1.0f / l1;
        size_t r0 = (size_t)(b * 2048) + rowg0;
        size_t r1 = (size_t)(b * 2048) + rowg1;
#pragma unroll
        for (int nt = 0; nt < 8; ++nt) {
            int col = h * 64 + nt * 8 + tg * 2;
            float a0 = o[nt][0] * inv0, a1 = o[nt][1] * inv0;
            float b0 = o[nt][2] * inv1, b1 = o[nt][3] * inv1;
            __nv_bfloat16 ah0 = __float2bfloat16(a0), ah1 = __float2bfloat16(a1);
            __nv_bfloat16 bh0 = __float2bfloat16(b0), bh1 = __float2bfloat16(b1);
            uint32_t ahi = pk(ah0, ah1);
            uint32_t alo = pkf(a0 - __bfloat162float(ah0), a1 - __bfloat162float(ah1));
            uint32_t bhi = pk(bh0, bh1);
            uint32_t blo = pkf(b0 - __bfloat162float(bh0), b1 - __bfloat162float(bh1));
            __nv_bfloat16* p0 = Eo + r0 * K3 + col;
            __nv_bfloat16* p1 = Eo + r1 * K3 + col;
            *(uint32_t*)(p0)        = ahi;
            *(uint32_t*)(p0 + 1024) = alo;
            *(uint32_t*)(p0 + 2048) = ahi;
            *(uint32_t*)(p1)        = bhi;
            *(uint32_t*)(p1 + 1024) = blo;
            *(uint32_t*)(p1 + 2048) = bhi;
        }

        __syncthreads();   // protect Q/K/V smem before next phase overwrites
    }
}

// ---------------------------------------------------------------------------
// launch
// ---------------------------------------------------------------------------
extern "C" void kernel_launch(void* const* d_in, const int* in_sizes, int n_in,
                              void* d_out, int out_size) {
    (void)in_sizes; (void)n_in; (void)out_size;
    const float* x    = (const float*)d_in[0];
    const float* wqkv = (const float*)d_in[1];
    const float* w0   = (const float*)d_in[2];
    float* out = (float*)d_out;

    __nv_bfloat16 *a2, *w2, *qd, *kd, *vd;
    cudaGetSymbolAddress((void**)&a2, g_a2);
    cudaGetSymbolAddress((void**)&w2, g_w2);
    cudaGetSymbolAddress((void**)&qd, g_q);
    cudaGetSymbolAddress((void**)&kd, g_k);
    cudaGetSymbolAddress((void**)&vd, g_v);

    cudaFuncSetAttribute(gemm_mma,
                         cudaFuncAttributeMaxDynamicSharedMemorySize, GEMM_SMEM);
    cudaFuncSetAttribute(attn_mma5,
                         cudaFuncAttributeMaxDynamicSharedMemorySize, ATT_SMEM);

    const int M = 4096;

    split3_kernel<<<(M * E_DIM / 4 + 255) / 256, 256>>>(x, a2, M, E_DIM, 1);
    split3_kernel<<<(3 * E_DIM * E_DIM / 4 + 255) / 256, 256>>>(wqkv, w2, 3 * E_DIM, E_DIM, 2);

    // gemm1: QKV, fused split epilogue -> Q'/K'/V' compact
    gemm_mma<<<dim3(3 * E_DIM / BN, M / BM), 256, GEMM_SMEM>>>(
        a2, w2, nullptr, M, 3 * E_DIM, K3, 1, qd, kd, vd);

    // attention -> E' (into g_a2); paired q-tiles: grid.x = 8
    attn_mma5<<<dim3(8, 16, 2), 256, ATT_SMEM>>>(qd, kd, vd, a2);

    split3_kernel<<<(E_DIM * E_DIM / 4 + 255) / 256, 256>>>(w0, w2, E_DIM, E_DIM, 2);

    // gemm2: out projection, fp32 epilogue
    gemm_mma<<<dim3(E_DIM / BN, M / BM), 256, GEMM_SMEM>>>(
        a2, w2, out, M, E_DIM, K3, 0, nullptr, nullptr, nullptr);
}